// round 1
// baseline (speedup 1.0000x reference)
#include <cuda_runtime.h>
#include <cuda_bf16.h>

// ---------------------------------------------------------------------------
// MultiResImplicitFeature: out[n, 56] =
//   [ sin(k*pi/2 * p_d) for k=1..4, d=0..2 ]   (cols 0..11, index k*3+d)
//   [ cos(...) same order ]                    (cols 12..23)
//   [ trilerp(grid_r, p) 8 feats, r=0..3 ]     (cols 24..55)
//
// Strategy: transpose each grid from [C,D,H,W] to channel-last [D,H,W,C]
// into __device__ scratch so every trilerp corner is ONE aligned 32B sector
// (2x LDG.128). All grids (76.7 MB) are L2-resident on GB300 (126 MB L2).
// ---------------------------------------------------------------------------

static constexpr int RES0 = 16, RES1 = 32, RES2 = 64, RES3 = 128;
static constexpr int S0 = RES0*RES0*RES0;            // 4096
static constexpr int S1 = RES1*RES1*RES1;            // 32768
static constexpr int S2 = RES2*RES2*RES2;            // 262144
static constexpr int S3 = RES3*RES3*RES3;            // 2097152
static constexpr long long OFF0 = 0;
static constexpr long long OFF1 = (long long)S0*8;               // 32768
static constexpr long long OFF2 = OFF1 + (long long)S1*8;        // 294912
static constexpr long long OFF3 = OFF2 + (long long)S2*8;        // 2392064
static constexpr long long GTOTAL = OFF3 + (long long)S3*8;      // 19169280 floats

__device__ __align__(256) float g_grids[GTOTAL];

// Transpose [8, S] (channel-major) -> [S, 8] (channel-last).
__global__ void transpose_cl_kernel(const float* __restrict__ in,
                                    float* __restrict__ out, int S) {
    int i = blockIdx.x * blockDim.x + threadIdx.x;
    if (i >= S) return;
    float v[8];
#pragma unroll
    for (int c = 0; c < 8; c++) v[c] = __ldg(in + (long long)c * S + i);
    float4* o = reinterpret_cast<float4*>(out + (long long)i * 8);
    o[0] = make_float4(v[0], v[1], v[2], v[3]);
    o[1] = make_float4(v[4], v[5], v[6], v[7]);
}

template <int R>
__device__ __forceinline__ void trilerp8(const float* __restrict__ g,
                                         float px, float py, float pz,
                                         float* __restrict__ acc) {
    const float scale = 0.5f * (float)(R - 1);
    float cx = (px + 1.0f) * scale;
    float cy = (py + 1.0f) * scale;
    float cz = (pz + 1.0f) * scale;
    float fx = floorf(cx), fy = floorf(cy), fz = floorf(cz);
    int x0 = (int)fx; x0 = max(0, min(x0, R - 1));
    int y0 = (int)fy; y0 = max(0, min(y0, R - 1));
    int z0 = (int)fz; z0 = max(0, min(z0, R - 1));
    int x1 = min(x0 + 1, R - 1);
    int y1 = min(y0 + 1, R - 1);
    int z1 = min(z0 + 1, R - 1);
    float wx = cx - fx, wy = cy - fy, wz = cz - fz;

    float wxs[2] = {1.0f - wx, wx};
    float wys[2] = {1.0f - wy, wy};
    float wzs[2] = {1.0f - wz, wz};
    int xs[2] = {x0, x1};
    int ys[2] = {y0, y1};
    int zs[2] = {z0, z1};

#pragma unroll
    for (int dz = 0; dz < 2; dz++) {
#pragma unroll
        for (int dy = 0; dy < 2; dy++) {
#pragma unroll
            for (int dx = 0; dx < 2; dx++) {
                long long idx = (((long long)zs[dz] * R + ys[dy]) * R + xs[dx]) << 3;
                const float4* p = reinterpret_cast<const float4*>(g + idx);
                float w = wzs[dz] * wys[dy] * wxs[dx];
                float4 a = __ldg(p);
                float4 b = __ldg(p + 1);
                acc[0] = fmaf(w, a.x, acc[0]);
                acc[1] = fmaf(w, a.y, acc[1]);
                acc[2] = fmaf(w, a.z, acc[2]);
                acc[3] = fmaf(w, a.w, acc[3]);
                acc[4] = fmaf(w, b.x, acc[4]);
                acc[5] = fmaf(w, b.y, acc[5]);
                acc[6] = fmaf(w, b.z, acc[6]);
                acc[7] = fmaf(w, b.w, acc[7]);
            }
        }
    }
}

__global__ void __launch_bounds__(256)
mrif_main_kernel(const float* __restrict__ x, float* __restrict__ out, int n) {
    int i = blockIdx.x * blockDim.x + threadIdx.x;
    if (i >= n) return;

    float px = __ldg(x + 3LL * i + 0);
    float py = __ldg(x + 3LL * i + 1);
    float pz = __ldg(x + 3LL * i + 2);

    float row[56];

    const float HPI = 1.57079632679489662f;
    float p[3] = {px, py, pz};
#pragma unroll
    for (int l = 0; l < 4; l++) {
#pragma unroll
        for (int d = 0; d < 3; d++) {
            float s, c;
            __sincosf(HPI * (float)(l + 1) * p[d], &s, &c);
            row[l * 3 + d] = s;
            row[12 + l * 3 + d] = c;
        }
    }

    float f[8];
#pragma unroll
    for (int c = 0; c < 8; c++) f[c] = 0.0f;
    trilerp8<RES0>(g_grids + OFF0, px, py, pz, f);
#pragma unroll
    for (int c = 0; c < 8; c++) row[24 + c] = f[c];

#pragma unroll
    for (int c = 0; c < 8; c++) f[c] = 0.0f;
    trilerp8<RES1>(g_grids + OFF1, px, py, pz, f);
#pragma unroll
    for (int c = 0; c < 8; c++) row[32 + c] = f[c];

#pragma unroll
    for (int c = 0; c < 8; c++) f[c] = 0.0f;
    trilerp8<RES2>(g_grids + OFF2, px, py, pz, f);
#pragma unroll
    for (int c = 0; c < 8; c++) row[40 + c] = f[c];

#pragma unroll
    for (int c = 0; c < 8; c++) f[c] = 0.0f;
    trilerp8<RES3>(g_grids + OFF3, px, py, pz, f);
#pragma unroll
    for (int c = 0; c < 8; c++) row[48 + c] = f[c];

    // 56 floats = 14 aligned float4 stores (row stride 224 B, 16B aligned)
    float4* o = reinterpret_cast<float4*>(out + (long long)i * 56);
#pragma unroll
    for (int k = 0; k < 14; k++) {
        o[k] = make_float4(row[4 * k], row[4 * k + 1], row[4 * k + 2], row[4 * k + 3]);
    }
}

extern "C" void kernel_launch(void* const* d_in, const int* in_sizes, int n_in,
                              void* d_out, int out_size) {
    const float* x  = (const float*)d_in[0];
    const float* g0 = (const float*)d_in[1];
    const float* g1 = (const float*)d_in[2];
    const float* g2 = (const float*)d_in[3];
    const float* g3 = (const float*)d_in[4];
    float* out = (float*)d_out;

    int n = in_sizes[0] / 3;

    float* gbase = nullptr;
    cudaGetSymbolAddress((void**)&gbase, g_grids);

    const int TT = 256;
    transpose_cl_kernel<<<(S0 + TT - 1) / TT, TT>>>(g0, gbase + OFF0, S0);
    transpose_cl_kernel<<<(S1 + TT - 1) / TT, TT>>>(g1, gbase + OFF1, S1);
    transpose_cl_kernel<<<(S2 + TT - 1) / TT, TT>>>(g2, gbase + OFF2, S2);
    transpose_cl_kernel<<<(S3 + TT - 1) / TT, TT>>>(g3, gbase + OFF3, S3);

    mrif_main_kernel<<<(n + 255) / 256, 256>>>(x, out, n);
}

// round 2
// speedup vs baseline: 1.2567x; 1.2567x over previous
#include <cuda_runtime.h>
#include <cuda_fp16.h>
#include <cuda_bf16.h>

// ---------------------------------------------------------------------------
// MultiResImplicitFeature: out[n, 56] =
//   cols 0..11  : sin(k*pi/2 * p_d), k=1..4, d=0..2 (index (k-1)*3+d)
//   cols 12..23 : cos(same)
//   cols 24..55 : trilerp(grid_r, p), 8 feats each, r=0..3
//
// R2 strategy:
//  - grids transposed to channel-last AND converted to fp16: one corner =
//    8 halfs = 16 B = single LDG.128. All grids = 38 MB, L2-resident.
//  - output written with __stcs (evict-first) so the 448 MB output stream
//    does not evict the grids from L2.
//  - progressive stores to keep register pressure / occupancy healthy.
// ---------------------------------------------------------------------------

static constexpr int RES0 = 16, RES1 = 32, RES2 = 64, RES3 = 128;
static constexpr int S0 = RES0*RES0*RES0;            // 4096
static constexpr int S1 = RES1*RES1*RES1;            // 32768
static constexpr int S2 = RES2*RES2*RES2;            // 262144
static constexpr int S3 = RES3*RES3*RES3;            // 2097152
static constexpr long long OFF0 = 0;
static constexpr long long OFF1 = (long long)S0*8;
static constexpr long long OFF2 = OFF1 + (long long)S1*8;
static constexpr long long OFF3 = OFF2 + (long long)S2*8;
static constexpr long long GTOTAL = OFF3 + (long long)S3*8;   // 19169280 halfs

__device__ __align__(256) __half g_grids[GTOTAL];

// Transpose [8, S] fp32 channel-major -> [S, 8] fp16 channel-last.
__global__ void transpose_cl_h_kernel(const float* __restrict__ in,
                                      __half* __restrict__ out, int S) {
    int i = blockIdx.x * blockDim.x + threadIdx.x;
    if (i >= S) return;
    __half v[8];
#pragma unroll
    for (int c = 0; c < 8; c++) v[c] = __float2half(__ldcs(in + (long long)c * S + i));
    *reinterpret_cast<uint4*>(out + (long long)i * 8) =
        *reinterpret_cast<const uint4*>(v);
}

template <int R>
__device__ __forceinline__ void trilerp8h(const __half* __restrict__ g,
                                          float px, float py, float pz,
                                          float* __restrict__ acc) {
    const float scale = 0.5f * (float)(R - 1);
    float cx = (px + 1.0f) * scale;
    float cy = (py + 1.0f) * scale;
    float cz = (pz + 1.0f) * scale;
    float fx = floorf(cx), fy = floorf(cy), fz = floorf(cz);
    int x0 = (int)fx; x0 = max(0, min(x0, R - 1));
    int y0 = (int)fy; y0 = max(0, min(y0, R - 1));
    int z0 = (int)fz; z0 = max(0, min(z0, R - 1));
    int x1 = min(x0 + 1, R - 1);
    int y1 = min(y0 + 1, R - 1);
    int z1 = min(z0 + 1, R - 1);
    float wx = cx - fx, wy = cy - fy, wz = cz - fz;

    float wxs[2] = {1.0f - wx, wx};
    float wys[2] = {1.0f - wy, wy};
    float wzs[2] = {1.0f - wz, wz};
    int xs[2] = {x0, x1};
    int ys[2] = {y0, y1};
    int zs[2] = {z0, z1};

#pragma unroll
    for (int dz = 0; dz < 2; dz++) {
#pragma unroll
        for (int dy = 0; dy < 2; dy++) {
            long long rowbase = ((long long)zs[dz] * R + ys[dy]) * R;
#pragma unroll
            for (int dx = 0; dx < 2; dx++) {
                long long idx = (rowbase + xs[dx]) << 3;     // 8 halfs per voxel
                uint4 v = __ldg(reinterpret_cast<const uint4*>(g + idx));
                float w = wzs[dz] * wys[dy] * wxs[dx];
                float2 f0 = __half22float2(*reinterpret_cast<__half2*>(&v.x));
                float2 f1 = __half22float2(*reinterpret_cast<__half2*>(&v.y));
                float2 f2 = __half22float2(*reinterpret_cast<__half2*>(&v.z));
                float2 f3 = __half22float2(*reinterpret_cast<__half2*>(&v.w));
                acc[0] = fmaf(w, f0.x, acc[0]);
                acc[1] = fmaf(w, f0.y, acc[1]);
                acc[2] = fmaf(w, f1.x, acc[2]);
                acc[3] = fmaf(w, f1.y, acc[3]);
                acc[4] = fmaf(w, f2.x, acc[4]);
                acc[5] = fmaf(w, f2.y, acc[5]);
                acc[6] = fmaf(w, f3.x, acc[6]);
                acc[7] = fmaf(w, f3.y, acc[7]);
            }
        }
    }
}

__global__ void __launch_bounds__(256)
mrif_main_kernel(const float* __restrict__ x, float* __restrict__ out, int n) {
    int i = blockIdx.x * blockDim.x + threadIdx.x;
    if (i >= n) return;

    float px = __ldg(x + 3LL * i + 0);
    float py = __ldg(x + 3LL * i + 1);
    float pz = __ldg(x + 3LL * i + 2);

    float* orow = out + (long long)i * 56;

    // ---- Fourier features: sin cols 0..11, cos cols 12..23 ----
    {
        const float HPI = 1.57079632679489662f;
        float sc[24];
        float p[3] = {px, py, pz};
#pragma unroll
        for (int l = 0; l < 4; l++) {
#pragma unroll
            for (int d = 0; d < 3; d++) {
                float s, c;
                __sincosf(HPI * (float)(l + 1) * p[d], &s, &c);
                sc[l * 3 + d] = s;
                sc[12 + l * 3 + d] = c;
            }
        }
#pragma unroll
        for (int k = 0; k < 6; k++) {
            __stcs(reinterpret_cast<float4*>(orow) + k,
                   make_float4(sc[4*k], sc[4*k+1], sc[4*k+2], sc[4*k+3]));
        }
    }

    // ---- 4 multires trilerps, stored progressively ----
    float f[8];

#pragma unroll
    for (int c = 0; c < 8; c++) f[c] = 0.0f;
    trilerp8h<RES0>(g_grids + OFF0, px, py, pz, f);
    __stcs(reinterpret_cast<float4*>(orow + 24),     make_float4(f[0], f[1], f[2], f[3]));
    __stcs(reinterpret_cast<float4*>(orow + 24) + 1, make_float4(f[4], f[5], f[6], f[7]));

#pragma unroll
    for (int c = 0; c < 8; c++) f[c] = 0.0f;
    trilerp8h<RES1>(g_grids + OFF1, px, py, pz, f);
    __stcs(reinterpret_cast<float4*>(orow + 32),     make_float4(f[0], f[1], f[2], f[3]));
    __stcs(reinterpret_cast<float4*>(orow + 32) + 1, make_float4(f[4], f[5], f[6], f[7]));

#pragma unroll
    for (int c = 0; c < 8; c++) f[c] = 0.0f;
    trilerp8h<RES2>(g_grids + OFF2, px, py, pz, f);
    __stcs(reinterpret_cast<float4*>(orow + 40),     make_float4(f[0], f[1], f[2], f[3]));
    __stcs(reinterpret_cast<float4*>(orow + 40) + 1, make_float4(f[4], f[5], f[6], f[7]));

#pragma unroll
    for (int c = 0; c < 8; c++) f[c] = 0.0f;
    trilerp8h<RES3>(g_grids + OFF3, px, py, pz, f);
    __stcs(reinterpret_cast<float4*>(orow + 48),     make_float4(f[0], f[1], f[2], f[3]));
    __stcs(reinterpret_cast<float4*>(orow + 48) + 1, make_float4(f[4], f[5], f[6], f[7]));
}

extern "C" void kernel_launch(void* const* d_in, const int* in_sizes, int n_in,
                              void* d_out, int out_size) {
    const float* x  = (const float*)d_in[0];
    const float* g0 = (const float*)d_in[1];
    const float* g1 = (const float*)d_in[2];
    const float* g2 = (const float*)d_in[3];
    const float* g3 = (const float*)d_in[4];
    float* out = (float*)d_out;

    int n = in_sizes[0] / 3;

    __half* gbase = nullptr;
    cudaGetSymbolAddress((void**)&gbase, g_grids);

    const int TT = 256;
    transpose_cl_h_kernel<<<(S0 + TT - 1) / TT, TT>>>(g0, gbase + OFF0, S0);
    transpose_cl_h_kernel<<<(S1 + TT - 1) / TT, TT>>>(g1, gbase + OFF1, S1);
    transpose_cl_h_kernel<<<(S2 + TT - 1) / TT, TT>>>(g2, gbase + OFF2, S2);
    transpose_cl_h_kernel<<<(S3 + TT - 1) / TT, TT>>>(g3, gbase + OFF3, S3);

    mrif_main_kernel<<<(n + 255) / 256, 256>>>(x, out, n);
}